// round 10
// baseline (speedup 1.0000x reference)
#include <cuda_runtime.h>
#include <cuda_fp16.h>
#include <math.h>
#include <stdint.h>

// ---------------- problem constants ----------------
#define T_TOK   16384
#define DIM     768
#define FF      2048
#define NE      8
#define SLOTS   (2*T_TOK)
#define BM      128
#define ROWS_PAD_MAX (SLOTS + NE*BM)   // 33792
#define ROW_TILES    (ROWS_PAD_MAX/BM) // 264

// GEMM tiling
#define GBM 128
#define GBN 128
#define GBK 32                  // K elements per stage chunk (64 bytes/row fp16)
#define ROWB 80                 // padded row stride bytes (64 data + 16 pad)
#define MATB (128*ROWB)         // 10240 bytes per 128-row matrix per stage
#define HMATB (64*ROWB)         // 5120 bytes per 64-row matrix per stage
#define STAGEB (2*MATB)         // 20480: A + B   (gated: A + B1 + B3 = same size)
#define STAGES 3
#define SM_BIAS (STAGES*STAGEB) // 61440
#define SM_TOTAL (SM_BIAS + 512)

// ---------------- device scratch ----------------
__device__ __half g_xh [(size_t)T_TOK * DIM];
__device__ __half g_f1h[(size_t)NE * FF * DIM];
__device__ __half g_f2h[(size_t)NE * DIM * FF];
__device__ __half g_w1h[(size_t)FF * DIM];
__device__ __half g_w3h[(size_t)FF * DIM];
__device__ __half g_w2h[(size_t)DIM * FF];
__device__ __half g_H  [(size_t)ROWS_PAD_MAX * FF];
__device__ __half g_Gp [(size_t)T_TOK * FF];
__device__ float g_Y [(size_t)ROWS_PAD_MAX * DIM];
__device__ int   g_rowtoken[ROWS_PAD_MAX];
__device__ int   g_rowmap[SLOTS];
__device__ float g_slotw[SLOTS];
__device__ int   g_slote[SLOTS];
__device__ int   g_counts[NE];
__device__ int   g_cursor[NE];
__device__ int   g_base[NE+1];

__device__ __forceinline__ float gelu_exact(float v) {
    return 0.5f * v * (1.0f + erff(v * 0.7071067811865475f));
}

// ---------------- PTX helpers (sm_80+ portable) ----------------
__device__ __forceinline__ uint32_t smem_u32(const void* p) {
    uint32_t a;
    asm("{ .reg .u64 t; cvta.to.shared.u64 t, %1; cvt.u32.u64 %0, t; }" : "=r"(a) : "l"(p));
    return a;
}
#define CP16(sa, gp) asm volatile("cp.async.cg.shared.global [%0], [%1], 16;" :: "r"(sa), "l"(gp))
#define CP_COMMIT()  asm volatile("cp.async.commit_group;" ::: "memory")
#define CP_WAIT2()   asm volatile("cp.async.wait_group 2;" ::: "memory")

#define LDSM4(r, a) \
    asm volatile("ldmatrix.sync.aligned.m8n8.x4.shared.b16 {%0,%1,%2,%3}, [%4];" \
        : "=r"((r)[0]), "=r"((r)[1]), "=r"((r)[2]), "=r"((r)[3]) : "r"(a))

__device__ __forceinline__ void mma_f16(float* c, const uint32_t* a, const uint32_t* b) {
    asm volatile(
        "mma.sync.aligned.m16n8k16.row.col.f32.f16.f16.f32 "
        "{%0,%1,%2,%3}, {%4,%5,%6,%7}, {%8,%9}, {%0,%1,%2,%3};"
        : "+f"(c[0]), "+f"(c[1]), "+f"(c[2]), "+f"(c[3])
        : "r"(a[0]), "r"(a[1]), "r"(a[2]), "r"(a[3]), "r"(b[0]), "r"(b[1]));
}

// ---------------- small kernels ----------------
__global__ void init_kernel() {
    int i = blockIdx.x * blockDim.x + threadIdx.x;
    if (i < ROWS_PAD_MAX) g_rowtoken[i] = -1;
    if (i < NE) { g_counts[i] = 0; g_cursor[i] = 0; }
}

// gate + fused x->fp16 conversion
__global__ __launch_bounds__(256) void gate_kernel(const float* __restrict__ x,
                                                   const float* __restrict__ gw) {
    __shared__ float sgw[NE * DIM];
    for (int i = threadIdx.x; i < NE * DIM; i += 256) sgw[i] = gw[i];
    __syncthreads();
    int warp = threadIdx.x >> 5, lane = threadIdx.x & 31;
    int t = blockIdx.x * 8 + warp;
    if (t >= T_TOK) return;
    const float* xr = x + (size_t)t * DIM;
    __half* xo = g_xh + (size_t)t * DIM;
    float xv[24];
#pragma unroll
    for (int j = 0; j < 24; j++) {
        xv[j] = xr[lane + 32 * j];
        xo[lane + 32 * j] = __float2half_rn(xv[j]);
    }
    float logit[NE];
#pragma unroll
    for (int e = 0; e < NE; e++) {
        float p = 0.f;
#pragma unroll
        for (int j = 0; j < 24; j++) p += xv[j] * sgw[e * DIM + lane + 32 * j];
#pragma unroll
        for (int off = 16; off > 0; off >>= 1) p += __shfl_down_sync(0xffffffffu, p, off);
        logit[e] = p;
    }
    if (lane == 0) {
        float m = logit[0];
#pragma unroll
        for (int e = 1; e < NE; e++) m = fmaxf(m, logit[e]);
        int a = 0;
#pragma unroll
        for (int e = 1; e < NE; e++) if (logit[e] > logit[a]) a = e;
        int b = (a == 0) ? 1 : 0;
#pragma unroll
        for (int e = 0; e < NE; e++) { if (e == a || e == b) continue; if (logit[e] > logit[b]) b = e; }
        float pa = expf(logit[a] - m), pb = expf(logit[b] - m);
        float inv = 1.f / (pa + pb);
        g_slote[2 * t] = a;  g_slote[2 * t + 1] = b;
        g_slotw[2 * t] = pa * inv;  g_slotw[2 * t + 1] = pb * inv;
        atomicAdd(&g_counts[a], 1);
        atomicAdd(&g_counts[b], 1);
    }
}

__global__ void scan_kernel() {
    if (threadIdx.x == 0 && blockIdx.x == 0) {
        int b = 0; g_base[0] = 0;
        for (int e = 0; e < NE; e++) {
            b += ((g_counts[e] + BM - 1) / BM) * BM;
            g_base[e + 1] = b;
        }
    }
}

__global__ void assign_kernel() {
    int t = blockIdx.x * blockDim.x + threadIdx.x;
    if (t >= T_TOK) return;
#pragma unroll
    for (int k = 0; k < 2; k++) {
        int e = g_slote[2 * t + k];
        int pos = atomicAdd(&g_cursor[e], 1);
        int row = g_base[e] + pos;
        g_rowmap[2 * t + k] = row;
        g_rowtoken[row] = t;
    }
}

// fp32 -> fp16 conversion
__global__ void conv_kernel(const float* __restrict__ s,
                            __half* __restrict__ o, int n4) {
    int i = blockIdx.x * blockDim.x + threadIdx.x;
    if (i >= n4) return;
    float4 v = ((const float4*)s)[i];
    __half h[4];
    h[0] = __float2half_rn(v.x); h[1] = __float2half_rn(v.y);
    h[2] = __float2half_rn(v.z); h[3] = __float2half_rn(v.w);
    ((uint2*)o)[i] = *(uint2*)h;
}

// vectorized combine: out += w0*Y[row0] + w1*Y[row1], float4 lanes
__global__ void combine_kernel(float* __restrict__ out) {
    int i = blockIdx.x * blockDim.x + threadIdx.x;
    const int n4 = T_TOK * (DIM / 4);
    if (i >= n4) return;
    int t = i / (DIM / 4);
    int c4 = i - t * (DIM / 4);
    float4 v = ((const float4*)out)[i];
    int r0 = g_rowmap[2 * t], r1 = g_rowmap[2 * t + 1];
    float w0 = g_slotw[2 * t], w1 = g_slotw[2 * t + 1];
    float4 y0 = *(const float4*)&g_Y[(size_t)r0 * DIM + c4 * 4];
    float4 y1 = *(const float4*)&g_Y[(size_t)r1 * DIM + c4 * 4];
    v.x += w0 * y0.x + w1 * y1.x;
    v.y += w0 * y0.y + w1 * y1.y;
    v.z += w0 * y0.z + w1 * y1.z;
    v.w += w0 * y0.w + w1 * y1.w;
    ((float4*)out)[i] = v;
}

// ---------------- mma.sync fp16 GEMM (R8-proven schedule) ----------------
// C[M,N] = A[M,K] x B[N,K]^T + bias
// MODE 0: gelu(acc+bias) -> fp16 Ch ;  MODE 1: acc+bias -> fp32 Cf
template<int MODE>
__global__ __launch_bounds__(256, 2) void mma_gemm_kernel(
    const __half* __restrict__ A, const __half* __restrict__ B,
    const float* __restrict__ bias,
    float* __restrict__ Cf, __half* __restrict__ Ch,
    int K, int N, int expert_mode, int gather)
{
    extern __shared__ char smem[];
    uint32_t sb = smem_u32(smem);
    int tid = threadIdx.x;

    int rstart = blockIdx.x * GBM;
    int n0 = blockIdx.y * GBN;

    if (expert_mode) {
        if (rstart >= g_base[NE]) return;
        int e = 0;
#pragma unroll
        for (int i = 0; i < NE; i++) if (rstart >= g_base[i + 1]) e = i + 1;
        B += (size_t)e * N * K;
        bias += (size_t)e * N;
    }

    // loads: thread t loads row t/2, 32B half (t&1)
    int lrow = tid >> 1;
    int lcb  = (tid & 1) * 32;
    int arow_g;
    if (gather) {
        int tok = g_rowtoken[rstart + lrow];
        arow_g = (tok < 0) ? 0 : tok;
    } else {
        arow_g = rstart + lrow;
    }
    const char* pA = (const char*)(A + (size_t)arow_g * K) + lcb;
    const char* pB = (const char*)(B + (size_t)(n0 + lrow) * K) + lcb;
    uint32_t sA = sb + (uint32_t)(lrow * ROWB + lcb);

    if (tid < 128) ((float*)(smem + SM_BIAS))[tid] = bias[n0 + tid];

    int nk = K / GBK;

#define ISSUE(kc, s) do { \
    uint32_t o = (uint32_t)(s) * STAGEB; \
    size_t g = (size_t)(kc) * 64; \
    CP16(sA + o,          pA + g); CP16(sA + o + 16,        pA + g + 16); \
    CP16(sA + o + MATB,   pB + g); CP16(sA + o + MATB + 16, pB + g + 16); \
    CP_COMMIT(); } while (0)

    ISSUE(0, 0);
    ISSUE(1, 1);
    ISSUE(2, 2);

    int wid = tid >> 5, lane = tid & 31;
    int wm = (wid & 3) * 32;
    int wn = (wid >> 2) * 64;
    int lq = lane >> 2;
    int lr = lane & 3;

    uint32_t aoff[2], boff[4];
#pragma unroll
    for (int m = 0; m < 2; m++)
        aoff[m] = (uint32_t)((wm + m * 16 + (lane & 15)) * ROWB + ((lane >> 4) << 4));
#pragma unroll
    for (int p = 0; p < 4; p++)
        boff[p] = (uint32_t)((wn + p * 16 + (lane & 7) + ((lane & 16) ? 8 : 0)) * ROWB
                             + ((lane & 8) ? 16 : 0));

    float acc[2][8][4];
#pragma unroll
    for (int m = 0; m < 2; m++)
#pragma unroll
        for (int n = 0; n < 8; n++)
#pragma unroll
            for (int j = 0; j < 4; j++) acc[m][n][j] = 0.f;

    for (int kc = 0; kc < nk; kc++) {
        CP_WAIT2();
        __syncthreads();
        uint32_t st = sb + (uint32_t)(kc % STAGES) * STAGEB;
#pragma unroll
        for (int ks = 0; ks < 2; ks++) {
            uint32_t ko = (uint32_t)(ks * 32);
            uint32_t a[2][4];
            LDSM4(a[0], st + aoff[0] + ko);
            LDSM4(a[1], st + aoff[1] + ko);
#pragma unroll
            for (int p = 0; p < 4; p++) {
                uint32_t bh[4];
                LDSM4(bh, st + MATB + boff[p] + ko);
#pragma unroll
                for (int m = 0; m < 2; m++) {
                    mma_f16(acc[m][2 * p],     a[m], bh);
                    mma_f16(acc[m][2 * p + 1], a[m], bh + 2);
                }
            }
        }
        __syncthreads();
        if (kc + STAGES < nk) { ISSUE(kc + STAGES, kc % STAGES); }
        else { CP_COMMIT(); }
    }
#undef ISSUE

    const float* sbias = (const float*)(smem + SM_BIAS);
#pragma unroll
    for (int m = 0; m < 2; m++) {
        int r0 = rstart + wm + m * 16 + lq;
#pragma unroll
        for (int n = 0; n < 8; n++) {
            int col = wn + n * 8 + lr * 2;
            float b0 = sbias[col], b1 = sbias[col + 1];
            int gc = n0 + col;
            float v00 = acc[m][n][0] + b0, v01 = acc[m][n][1] + b1;
            float v10 = acc[m][n][2] + b0, v11 = acc[m][n][3] + b1;
            if (MODE == 1) {
                *(float2*)&Cf[(size_t)r0 * N + gc]       = make_float2(v00, v01);
                *(float2*)&Cf[(size_t)(r0 + 8) * N + gc] = make_float2(v10, v11);
            } else {
                __half2 h0, h1;
                h0.x = __float2half_rn(gelu_exact(v00));
                h0.y = __float2half_rn(gelu_exact(v01));
                h1.x = __float2half_rn(gelu_exact(v10));
                h1.y = __float2half_rn(gelu_exact(v11));
                *(__half2*)&Ch[(size_t)r0 * N + gc]       = h0;
                *(__half2*)&Ch[(size_t)(r0 + 8) * N + gc] = h1;
            }
        }
    }
}

// ---------------- fused w1/w3 gated MLP front (R8-proven schedule) ----------------
__global__ __launch_bounds__(256, 2) void gated_mma_kernel(
    const __half* __restrict__ A,
    const __half* __restrict__ B1, const __half* __restrict__ B3,
    const float* __restrict__ bias1, const float* __restrict__ bias3,
    __half* __restrict__ Gp)
{
    extern __shared__ char smem[];
    uint32_t sb = smem_u32(smem);
    int tid = threadIdx.x;
    int rstart = blockIdx.x * GBM;
    int n0 = blockIdx.y * 64;

    int lrow = tid >> 1;
    int lcb  = (tid & 1) * 32;
    const char* pA = (const char*)(A + (size_t)(rstart + lrow) * DIM) + lcb;
    uint32_t sA = sb + (uint32_t)(lrow * ROWB + lcb);
    int brow = tid >> 2;
    int bq   = (tid & 3) * 16;
    const char* pB1 = (const char*)(B1 + (size_t)(n0 + brow) * DIM) + bq;
    const char* pB3 = (const char*)(B3 + (size_t)(n0 + brow) * DIM) + bq;
    uint32_t sB = sb + (uint32_t)(brow * ROWB + bq);

    if (tid < 64) {
        ((float*)(smem + SM_BIAS))[tid]      = bias1[n0 + tid];
        ((float*)(smem + SM_BIAS))[64 + tid] = bias3[n0 + tid];
    }

    const int nk = DIM / GBK;

#define ISSUE_G(kc, s) do { \
    uint32_t o = (uint32_t)(s) * STAGEB; \
    size_t g = (size_t)(kc) * 64; \
    CP16(sA + o,                pA  + g); CP16(sA + o + 16, pA + g + 16); \
    CP16(sB + o + MATB,         pB1 + g); \
    CP16(sB + o + MATB + HMATB, pB3 + g); \
    CP_COMMIT(); } while (0)

    ISSUE_G(0, 0);
    ISSUE_G(1, 1);
    ISSUE_G(2, 2);

    int wid = tid >> 5, lane = tid & 31;
    int wm = (wid & 3) * 32;
    int wn = (wid >> 2) * 32;
    int lq = lane >> 2;
    int lr = lane & 3;

    uint32_t aoff[2], boff[2];
#pragma unroll
    for (int m = 0; m < 2; m++)
        aoff[m] = (uint32_t)((wm + m * 16 + (lane & 15)) * ROWB + ((lane >> 4) << 4));
#pragma unroll
    for (int p = 0; p < 2; p++)
        boff[p] = (uint32_t)((wn + p * 16 + (lane & 7) + ((lane & 16) ? 8 : 0)) * ROWB
                             + ((lane & 8) ? 16 : 0));

    float acc1[2][4][4], acc3[2][4][4];
#pragma unroll
    for (int m = 0; m < 2; m++)
#pragma unroll
        for (int n = 0; n < 4; n++)
#pragma unroll
            for (int j = 0; j < 4; j++) { acc1[m][n][j] = 0.f; acc3[m][n][j] = 0.f; }

    for (int kc = 0; kc < nk; kc++) {
        CP_WAIT2();
        __syncthreads();
        uint32_t st = sb + (uint32_t)(kc % STAGES) * STAGEB;
#pragma unroll
        for (int ks = 0; ks < 2; ks++) {
            uint32_t ko = (uint32_t)(ks * 32);
            uint32_t a[2][4];
            LDSM4(a[0], st + aoff[0] + ko);
            LDSM4(a[1], st + aoff[1] + ko);
#pragma unroll
            for (int p = 0; p < 2; p++) {
                uint32_t b1[4], b3[4];
                LDSM4(b1, st + MATB + boff[p] + ko);
                LDSM4(b3, st + MATB + HMATB + boff[p] + ko);
#pragma unroll
                for (int m = 0; m < 2; m++) {
                    mma_f16(acc1[m][2 * p],     a[m], b1);
                    mma_f16(acc1[m][2 * p + 1], a[m], b1 + 2);
                    mma_f16(acc3[m][2 * p],     a[m], b3);
                    mma_f16(acc3[m][2 * p + 1], a[m], b3 + 2);
                }
            }
        }
        __syncthreads();
        if (kc + STAGES < nk) { ISSUE_G(kc + STAGES, kc % STAGES); }
        else { CP_COMMIT(); }
    }
#undef ISSUE_G

    const float* b1s = (const float*)(smem + SM_BIAS);
    const float* b3s = b1s + 64;
#pragma unroll
    for (int m = 0; m < 2; m++) {
        int r0 = rstart + wm + m * 16 + lq;
#pragma unroll
        for (int n = 0; n < 4; n++) {
            int col = wn + n * 8 + lr * 2;
            float c10 = b1s[col], c11 = b1s[col + 1];
            float c30 = b3s[col], c31 = b3s[col + 1];
            int gc = n0 + col;
            __half2 h0, h1;
            h0.x = __float2half_rn(gelu_exact(acc1[m][n][0] + c10) * (acc3[m][n][0] + c30));
            h0.y = __float2half_rn(gelu_exact(acc1[m][n][1] + c11) * (acc3[m][n][1] + c31));
            h1.x = __float2half_rn(gelu_exact(acc1[m][n][2] + c10) * (acc3[m][n][2] + c30));
            h1.y = __float2half_rn(gelu_exact(acc1[m][n][3] + c11) * (acc3[m][n][3] + c31));
            *(__half2*)&Gp[(size_t)r0 * FF + gc]       = h0;
            *(__half2*)&Gp[(size_t)(r0 + 8) * FF + gc] = h1;
        }
    }
}

// ---------------- launch ----------------
extern "C" void kernel_launch(void* const* d_in, const int* in_sizes, int n_in,
                              void* d_out, int out_size) {
    const float* x      = (const float*)d_in[0];
    const float* gate_w = (const float*)d_in[1];
    const float* fc1_w  = (const float*)d_in[2];
    const float* fc1_b  = (const float*)d_in[3];
    const float* fc2_w  = (const float*)d_in[4];
    const float* fc2_b  = (const float*)d_in[5];
    const float* w1_w   = (const float*)d_in[6];
    const float* w1_b   = (const float*)d_in[7];
    const float* w3_w   = (const float*)d_in[8];
    const float* w3_b   = (const float*)d_in[9];
    const float* w2_w   = (const float*)d_in[10];
    const float* w2_b   = (const float*)d_in[11];
    float* out = (float*)d_out;

    cudaFuncSetAttribute(mma_gemm_kernel<0>, cudaFuncAttributeMaxDynamicSharedMemorySize, SM_TOTAL);
    cudaFuncSetAttribute(mma_gemm_kernel<1>, cudaFuncAttributeMaxDynamicSharedMemorySize, SM_TOTAL);
    cudaFuncSetAttribute(gated_mma_kernel,   cudaFuncAttributeMaxDynamicSharedMemorySize, SM_TOTAL);

    // routing metadata (gate also emits xh)
    init_kernel<<<(ROWS_PAD_MAX + 255) / 256, 256>>>();
    gate_kernel<<<T_TOK / 8, 256>>>(x, gate_w);
    scan_kernel<<<1, 32>>>();
    assign_kernel<<<(T_TOK + 255) / 256, 256>>>();

    __half* xh;  cudaGetSymbolAddress((void**)&xh,  g_xh);
    __half* f1h; cudaGetSymbolAddress((void**)&f1h, g_f1h);
    __half* f2h; cudaGetSymbolAddress((void**)&f2h, g_f2h);
    __half* w1h; cudaGetSymbolAddress((void**)&w1h, g_w1h);
    __half* w3h; cudaGetSymbolAddress((void**)&w3h, g_w3h);
    __half* w2h; cudaGetSymbolAddress((void**)&w2h, g_w2h);
    __half* Hh;  cudaGetSymbolAddress((void**)&Hh,  g_H);
    __half* Gp;  cudaGetSymbolAddress((void**)&Gp,  g_Gp);
    float* Yf;  cudaGetSymbolAddress((void**)&Yf,  g_Y);

    auto conv = [&](const float* s, __half* o, size_t n) {
        int n4 = (int)(n / 4);
        conv_kernel<<<(n4 + 255) / 256, 256>>>(s, o, n4);
    };
    conv(fc1_w, f1h, (size_t)NE * FF * DIM);
    conv(fc2_w, f2h, (size_t)NE * DIM * FF);
    conv(w1_w,  w1h, (size_t)FF * DIM);
    conv(w3_w,  w3h, (size_t)FF * DIM);
    conv(w2_w,  w2h, (size_t)DIM * FF);

    // routed experts
    mma_gemm_kernel<0><<<dim3(ROW_TILES, FF / GBN), 256, SM_TOTAL>>>(
        xh, f1h, fc1_b, nullptr, Hh, DIM, FF, 1, 1);
    mma_gemm_kernel<1><<<dim3(ROW_TILES, DIM / GBN), 256, SM_TOTAL>>>(
        Hh, f2h, fc2_b, Yf, nullptr, FF, DIM, 1, 0);

    // shared gated MLP: fused w1+w3+eltwise, then w2
    gated_mma_kernel<<<dim3(T_TOK / GBM, FF / 64), 256, SM_TOTAL>>>(
        xh, w1h, w3h, w1_b, w3_b, Gp);
    mma_gemm_kernel<1><<<dim3(T_TOK / GBM, DIM / GBN), 256, SM_TOTAL>>>(
        Gp, w2h, w2_b, out, nullptr, FF, DIM, 0, 0);

    // combine (vectorized)
    combine_kernel<<<(T_TOK * (DIM / 4) + 255) / 256, 256>>>(out);
}

// round 11
// speedup vs baseline: 1.4976x; 1.4976x over previous
#include <cuda_runtime.h>
#include <cuda_fp16.h>
#include <math.h>
#include <stdint.h>

// ---------------- problem constants ----------------
#define T_TOK   16384
#define DIM     768
#define FF      2048
#define NE      8
#define SLOTS   (2*T_TOK)
#define BM      128
#define ROWS_PAD_MAX (SLOTS + NE*BM)   // 33792
#define ROW_TILES    (ROWS_PAD_MAX/BM) // 264

// GEMM tiling
#define GBM 128
#define GBN 128
#define GBK 32                  // K elements per stage chunk (64 bytes/row fp16)
#define ROWB 80                 // padded row stride bytes (64 data + 16 pad)
#define MATB (128*ROWB)         // 10240 bytes per 128-row matrix per stage
#define HMATB (64*ROWB)         // 5120 bytes per 64-row matrix per stage
#define STAGEB (2*MATB)         // 20480: A + B   (gated: A + B1 + B3 = same size)
#define STAGES 3
#define SM_BIAS (STAGES*STAGEB) // 61440
#define SM_TOTAL (SM_BIAS + 512)

// conversion segment sizes in float4 units
#define C_X   (T_TOK*DIM/4)            // 3145728
#define C_F1  (NE*FF*DIM/4)            // 3145728
#define C_F2  (NE*DIM*FF/4)            // 3145728
#define C_W   (FF*DIM/4)               // 393216
#define O1 (C_X)
#define O2 (O1 + C_F1)
#define O3 (O2 + C_F2)
#define O4 (O3 + C_W)
#define O5 (O4 + C_W)
#define O6 (O5 + C_W)

// ---------------- device scratch ----------------
__device__ __half g_xh [(size_t)T_TOK * DIM];
__device__ __half g_f1h[(size_t)NE * FF * DIM];
__device__ __half g_f2h[(size_t)NE * DIM * FF];
__device__ __half g_w1h[(size_t)FF * DIM];
__device__ __half g_w3h[(size_t)FF * DIM];
__device__ __half g_w2h[(size_t)DIM * FF];
__device__ __half g_H  [(size_t)ROWS_PAD_MAX * FF];
__device__ __half g_Gp [(size_t)T_TOK * FF];
__device__ float g_Y [(size_t)ROWS_PAD_MAX * DIM];
__device__ int   g_rowtoken[ROWS_PAD_MAX];
__device__ int   g_rowmap[SLOTS];
__device__ float g_slotw[SLOTS];
__device__ int   g_slote[SLOTS];
__device__ int   g_counts[NE];
__device__ int   g_cursor[NE];
__device__ int   g_base[NE+1];

__device__ __forceinline__ float gelu_exact(float v) {
    return 0.5f * v * (1.0f + erff(v * 0.7071067811865475f));
}

// ---------------- PTX helpers (sm_80+ portable) ----------------
__device__ __forceinline__ uint32_t smem_u32(const void* p) {
    uint32_t a;
    asm("{ .reg .u64 t; cvta.to.shared.u64 t, %1; cvt.u32.u64 %0, t; }" : "=r"(a) : "l"(p));
    return a;
}
#define CP16(sa, gp) asm volatile("cp.async.cg.shared.global [%0], [%1], 16;" :: "r"(sa), "l"(gp))
#define CP_COMMIT()  asm volatile("cp.async.commit_group;" ::: "memory")
#define CP_WAIT2()   asm volatile("cp.async.wait_group 2;" ::: "memory")

#define LDSM4(r, a) \
    asm volatile("ldmatrix.sync.aligned.m8n8.x4.shared.b16 {%0,%1,%2,%3}, [%4];" \
        : "=r"((r)[0]), "=r"((r)[1]), "=r"((r)[2]), "=r"((r)[3]) : "r"(a))

__device__ __forceinline__ void mma_f16(float* c, const uint32_t* a, const uint32_t* b) {
    asm volatile(
        "mma.sync.aligned.m16n8k16.row.col.f32.f16.f16.f32 "
        "{%0,%1,%2,%3}, {%4,%5,%6,%7}, {%8,%9}, {%0,%1,%2,%3};"
        : "+f"(c[0]), "+f"(c[1]), "+f"(c[2]), "+f"(c[3])
        : "r"(a[0]), "r"(a[1]), "r"(a[2]), "r"(a[3]), "r"(b[0]), "r"(b[1]));
}

// ---------------- small kernels ----------------
__global__ void init_kernel() {
    int i = blockIdx.x * blockDim.x + threadIdx.x;
    if (i < ROWS_PAD_MAX) g_rowtoken[i] = -1;
    if (i < NE) { g_counts[i] = 0; g_cursor[i] = 0; }
}

// gate (R8-exact: no fused conversion)
__global__ __launch_bounds__(256) void gate_kernel(const float* __restrict__ x,
                                                   const float* __restrict__ gw) {
    __shared__ float sgw[NE * DIM];
    for (int i = threadIdx.x; i < NE * DIM; i += 256) sgw[i] = gw[i];
    __syncthreads();
    int warp = threadIdx.x >> 5, lane = threadIdx.x & 31;
    int t = blockIdx.x * 8 + warp;
    if (t >= T_TOK) return;
    const float* xr = x + (size_t)t * DIM;
    float xv[24];
#pragma unroll
    for (int j = 0; j < 24; j++) xv[j] = xr[lane + 32 * j];
    float logit[NE];
#pragma unroll
    for (int e = 0; e < NE; e++) {
        float p = 0.f;
#pragma unroll
        for (int j = 0; j < 24; j++) p += xv[j] * sgw[e * DIM + lane + 32 * j];
#pragma unroll
        for (int off = 16; off > 0; off >>= 1) p += __shfl_down_sync(0xffffffffu, p, off);
        logit[e] = p;
    }
    if (lane == 0) {
        float m = logit[0];
#pragma unroll
        for (int e = 1; e < NE; e++) m = fmaxf(m, logit[e]);
        int a = 0;
#pragma unroll
        for (int e = 1; e < NE; e++) if (logit[e] > logit[a]) a = e;
        int b = (a == 0) ? 1 : 0;
#pragma unroll
        for (int e = 0; e < NE; e++) { if (e == a || e == b) continue; if (logit[e] > logit[b]) b = e; }
        float pa = expf(logit[a] - m), pb = expf(logit[b] - m);
        float inv = 1.f / (pa + pb);
        g_slote[2 * t] = a;  g_slote[2 * t + 1] = b;
        g_slotw[2 * t] = pa * inv;  g_slotw[2 * t + 1] = pb * inv;
        atomicAdd(&g_counts[a], 1);
        atomicAdd(&g_counts[b], 1);
    }
}

__global__ void scan_kernel() {
    if (threadIdx.x == 0 && blockIdx.x == 0) {
        int b = 0; g_base[0] = 0;
        for (int e = 0; e < NE; e++) {
            b += ((g_counts[e] + BM - 1) / BM) * BM;
            g_base[e + 1] = b;
        }
    }
}

__global__ void assign_kernel() {
    int t = blockIdx.x * blockDim.x + threadIdx.x;
    if (t >= T_TOK) return;
#pragma unroll
    for (int k = 0; k < 2; k++) {
        int e = g_slote[2 * t + k];
        int pos = atomicAdd(&g_cursor[e], 1);
        int row = g_base[e] + pos;
        g_rowmap[2 * t + k] = row;
        g_rowtoken[row] = t;
    }
}

// single fused fp32 -> fp16 conversion over all 6 tensors
__global__ void conv6_kernel(const float* __restrict__ x,
                             const float* __restrict__ f1, const float* __restrict__ f2,
                             const float* __restrict__ w1, const float* __restrict__ w3,
                             const float* __restrict__ w2) {
    int i = blockIdx.x * blockDim.x + threadIdx.x;
    if (i >= O6) return;
    const float* s; __half* d; int off;
    if (i < O1)      { s = x;  d = g_xh;  off = i; }
    else if (i < O2) { s = f1; d = g_f1h; off = i - O1; }
    else if (i < O3) { s = f2; d = g_f2h; off = i - O2; }
    else if (i < O4) { s = w1; d = g_w1h; off = i - O3; }
    else if (i < O5) { s = w3; d = g_w3h; off = i - O4; }
    else             { s = w2; d = g_w2h; off = i - O5; }
    float4 v = ((const float4*)s)[off];
    __half h[4];
    h[0] = __float2half_rn(v.x); h[1] = __float2half_rn(v.y);
    h[2] = __float2half_rn(v.z); h[3] = __float2half_rn(v.w);
    ((uint2*)d)[off] = *(uint2*)h;
}

// combine (R8-exact: scalar)
__global__ void combine_kernel(float* __restrict__ out) {
    size_t i = (size_t)blockIdx.x * blockDim.x + threadIdx.x;
    if (i >= (size_t)T_TOK * DIM) return;
    int t = (int)(i / DIM), c = (int)(i % DIM);
    float v = out[i];
    int r0 = g_rowmap[2 * t], r1 = g_rowmap[2 * t + 1];
    v += g_slotw[2 * t]     * g_Y[(size_t)r0 * DIM + c];
    v += g_slotw[2 * t + 1] * g_Y[(size_t)r1 * DIM + c];
    out[i] = v;
}

// ---------------- mma.sync fp16 GEMM (R8-exact) ----------------
// C[M,N] = A[M,K] x B[N,K]^T + bias
// MODE 0: gelu(acc+bias) -> fp16 Ch ;  MODE 1: acc+bias -> fp32 Cf
template<int MODE>
__global__ __launch_bounds__(256, 2) void mma_gemm_kernel(
    const __half* __restrict__ A, const __half* __restrict__ B,
    const float* __restrict__ bias,
    float* __restrict__ Cf, __half* __restrict__ Ch,
    int K, int N, int expert_mode, int gather)
{
    extern __shared__ char smem[];
    uint32_t sb = smem_u32(smem);
    int tid = threadIdx.x;

    int rstart = blockIdx.x * GBM;
    int n0 = blockIdx.y * GBN;

    if (expert_mode) {
        if (rstart >= g_base[NE]) return;
        int e = 0;
#pragma unroll
        for (int i = 0; i < NE; i++) if (rstart >= g_base[i + 1]) e = i + 1;
        B += (size_t)e * N * K;
        bias += (size_t)e * N;
    }

    // loads: thread t loads row t/2, 32B half (t&1)
    int lrow = tid >> 1;
    int lcb  = (tid & 1) * 32;
    int arow_g;
    if (gather) {
        int tok = g_rowtoken[rstart + lrow];
        arow_g = (tok < 0) ? 0 : tok;
    } else {
        arow_g = rstart + lrow;
    }
    const char* pA = (const char*)(A + (size_t)arow_g * K) + lcb;
    const char* pB = (const char*)(B + (size_t)(n0 + lrow) * K) + lcb;
    uint32_t sA = sb + (uint32_t)(lrow * ROWB + lcb);

    if (tid < 128) ((float*)(smem + SM_BIAS))[tid] = bias[n0 + tid];

    int nk = K / GBK;

#define ISSUE(kc, s) do { \
    uint32_t o = (uint32_t)(s) * STAGEB; \
    size_t g = (size_t)(kc) * 64; \
    CP16(sA + o,          pA + g); CP16(sA + o + 16,        pA + g + 16); \
    CP16(sA + o + MATB,   pB + g); CP16(sA + o + MATB + 16, pB + g + 16); \
    CP_COMMIT(); } while (0)

    ISSUE(0, 0);
    ISSUE(1, 1);
    ISSUE(2, 2);

    int wid = tid >> 5, lane = tid & 31;
    int wm = (wid & 3) * 32;
    int wn = (wid >> 2) * 64;
    int lq = lane >> 2;
    int lr = lane & 3;

    uint32_t aoff[2], boff[4];
#pragma unroll
    for (int m = 0; m < 2; m++)
        aoff[m] = (uint32_t)((wm + m * 16 + (lane & 15)) * ROWB + ((lane >> 4) << 4));
#pragma unroll
    for (int p = 0; p < 4; p++)
        boff[p] = (uint32_t)((wn + p * 16 + (lane & 7) + ((lane & 16) ? 8 : 0)) * ROWB
                             + ((lane & 8) ? 16 : 0));

    float acc[2][8][4];
#pragma unroll
    for (int m = 0; m < 2; m++)
#pragma unroll
        for (int n = 0; n < 8; n++)
#pragma unroll
            for (int j = 0; j < 4; j++) acc[m][n][j] = 0.f;

    for (int kc = 0; kc < nk; kc++) {
        CP_WAIT2();
        __syncthreads();
        uint32_t st = sb + (uint32_t)(kc % STAGES) * STAGEB;
#pragma unroll
        for (int ks = 0; ks < 2; ks++) {
            uint32_t ko = (uint32_t)(ks * 32);
            uint32_t a[2][4];
            LDSM4(a[0], st + aoff[0] + ko);
            LDSM4(a[1], st + aoff[1] + ko);
#pragma unroll
            for (int p = 0; p < 4; p++) {
                uint32_t bh[4];
                LDSM4(bh, st + MATB + boff[p] + ko);
#pragma unroll
                for (int m = 0; m < 2; m++) {
                    mma_f16(acc[m][2 * p],     a[m], bh);
                    mma_f16(acc[m][2 * p + 1], a[m], bh + 2);
                }
            }
        }
        __syncthreads();
        if (kc + STAGES < nk) { ISSUE(kc + STAGES, kc % STAGES); }
        else { CP_COMMIT(); }
    }
#undef ISSUE

    const float* sbias = (const float*)(smem + SM_BIAS);
#pragma unroll
    for (int m = 0; m < 2; m++) {
        int r0 = rstart + wm + m * 16 + lq;
#pragma unroll
        for (int n = 0; n < 8; n++) {
            int col = wn + n * 8 + lr * 2;
            float b0 = sbias[col], b1 = sbias[col + 1];
            int gc = n0 + col;
            float v00 = acc[m][n][0] + b0, v01 = acc[m][n][1] + b1;
            float v10 = acc[m][n][2] + b0, v11 = acc[m][n][3] + b1;
            if (MODE == 1) {
                *(float2*)&Cf[(size_t)r0 * N + gc]       = make_float2(v00, v01);
                *(float2*)&Cf[(size_t)(r0 + 8) * N + gc] = make_float2(v10, v11);
            } else {
                __half2 h0, h1;
                h0.x = __float2half_rn(gelu_exact(v00));
                h0.y = __float2half_rn(gelu_exact(v01));
                h1.x = __float2half_rn(gelu_exact(v10));
                h1.y = __float2half_rn(gelu_exact(v11));
                *(__half2*)&Ch[(size_t)r0 * N + gc]       = h0;
                *(__half2*)&Ch[(size_t)(r0 + 8) * N + gc] = h1;
            }
        }
    }
}

// ---------------- fused w1/w3 gated MLP front (R8-exact) ----------------
__global__ __launch_bounds__(256, 2) void gated_mma_kernel(
    const __half* __restrict__ A,
    const __half* __restrict__ B1, const __half* __restrict__ B3,
    const float* __restrict__ bias1, const float* __restrict__ bias3,
    __half* __restrict__ Gp)
{
    extern __shared__ char smem[];
    uint32_t sb = smem_u32(smem);
    int tid = threadIdx.x;
    int rstart = blockIdx.x * GBM;
    int n0 = blockIdx.y * 64;

    int lrow = tid >> 1;
    int lcb  = (tid & 1) * 32;
    const char* pA = (const char*)(A + (size_t)(rstart + lrow) * DIM) + lcb;
    uint32_t sA = sb + (uint32_t)(lrow * ROWB + lcb);
    int brow = tid >> 2;
    int bq   = (tid & 3) * 16;
    const char* pB1 = (const char*)(B1 + (size_t)(n0 + brow) * DIM) + bq;
    const char* pB3 = (const char*)(B3 + (size_t)(n0 + brow) * DIM) + bq;
    uint32_t sB = sb + (uint32_t)(brow * ROWB + bq);

    if (tid < 64) {
        ((float*)(smem + SM_BIAS))[tid]      = bias1[n0 + tid];
        ((float*)(smem + SM_BIAS))[64 + tid] = bias3[n0 + tid];
    }

    const int nk = DIM / GBK;

#define ISSUE_G(kc, s) do { \
    uint32_t o = (uint32_t)(s) * STAGEB; \
    size_t g = (size_t)(kc) * 64; \
    CP16(sA + o,                pA  + g); CP16(sA + o + 16, pA + g + 16); \
    CP16(sB + o + MATB,         pB1 + g); \
    CP16(sB + o + MATB + HMATB, pB3 + g); \
    CP_COMMIT(); } while (0)

    ISSUE_G(0, 0);
    ISSUE_G(1, 1);
    ISSUE_G(2, 2);

    int wid = tid >> 5, lane = tid & 31;
    int wm = (wid & 3) * 32;
    int wn = (wid >> 2) * 32;
    int lq = lane >> 2;
    int lr = lane & 3;

    uint32_t aoff[2], boff[2];
#pragma unroll
    for (int m = 0; m < 2; m++)
        aoff[m] = (uint32_t)((wm + m * 16 + (lane & 15)) * ROWB + ((lane >> 4) << 4));
#pragma unroll
    for (int p = 0; p < 2; p++)
        boff[p] = (uint32_t)((wn + p * 16 + (lane & 7) + ((lane & 16) ? 8 : 0)) * ROWB
                             + ((lane & 8) ? 16 : 0));

    float acc1[2][4][4], acc3[2][4][4];
#pragma unroll
    for (int m = 0; m < 2; m++)
#pragma unroll
        for (int n = 0; n < 4; n++)
#pragma unroll
            for (int j = 0; j < 4; j++) { acc1[m][n][j] = 0.f; acc3[m][n][j] = 0.f; }

    for (int kc = 0; kc < nk; kc++) {
        CP_WAIT2();
        __syncthreads();
        uint32_t st = sb + (uint32_t)(kc % STAGES) * STAGEB;
#pragma unroll
        for (int ks = 0; ks < 2; ks++) {
            uint32_t ko = (uint32_t)(ks * 32);
            uint32_t a[2][4];
            LDSM4(a[0], st + aoff[0] + ko);
            LDSM4(a[1], st + aoff[1] + ko);
#pragma unroll
            for (int p = 0; p < 2; p++) {
                uint32_t b1[4], b3[4];
                LDSM4(b1, st + MATB + boff[p] + ko);
                LDSM4(b3, st + MATB + HMATB + boff[p] + ko);
#pragma unroll
                for (int m = 0; m < 2; m++) {
                    mma_f16(acc1[m][2 * p],     a[m], b1);
                    mma_f16(acc1[m][2 * p + 1], a[m], b1 + 2);
                    mma_f16(acc3[m][2 * p],     a[m], b3);
                    mma_f16(acc3[m][2 * p + 1], a[m], b3 + 2);
                }
            }
        }
        __syncthreads();
        if (kc + STAGES < nk) { ISSUE_G(kc + STAGES, kc % STAGES); }
        else { CP_COMMIT(); }
    }
#undef ISSUE_G

    const float* b1s = (const float*)(smem + SM_BIAS);
    const float* b3s = b1s + 64;
#pragma unroll
    for (int m = 0; m < 2; m++) {
        int r0 = rstart + wm + m * 16 + lq;
#pragma unroll
        for (int n = 0; n < 4; n++) {
            int col = wn + n * 8 + lr * 2;
            float c10 = b1s[col], c11 = b1s[col + 1];
            float c30 = b3s[col], c31 = b3s[col + 1];
            int gc = n0 + col;
            __half2 h0, h1;
            h0.x = __float2half_rn(gelu_exact(acc1[m][n][0] + c10) * (acc3[m][n][0] + c30));
            h0.y = __float2half_rn(gelu_exact(acc1[m][n][1] + c11) * (acc3[m][n][1] + c31));
            h1.x = __float2half_rn(gelu_exact(acc1[m][n][2] + c10) * (acc3[m][n][2] + c30));
            h1.y = __float2half_rn(gelu_exact(acc1[m][n][3] + c11) * (acc3[m][n][3] + c31));
            *(__half2*)&Gp[(size_t)r0 * FF + gc]       = h0;
            *(__half2*)&Gp[(size_t)(r0 + 8) * FF + gc] = h1;
        }
    }
}

// ---------------- launch ----------------
extern "C" void kernel_launch(void* const* d_in, const int* in_sizes, int n_in,
                              void* d_out, int out_size) {
    const float* x      = (const float*)d_in[0];
    const float* gate_w = (const float*)d_in[1];
    const float* fc1_w  = (const float*)d_in[2];
    const float* fc1_b  = (const float*)d_in[3];
    const float* fc2_w  = (const float*)d_in[4];
    const float* fc2_b  = (const float*)d_in[5];
    const float* w1_w   = (const float*)d_in[6];
    const float* w1_b   = (const float*)d_in[7];
    const float* w3_w   = (const float*)d_in[8];
    const float* w3_b   = (const float*)d_in[9];
    const float* w2_w   = (const float*)d_in[10];
    const float* w2_b   = (const float*)d_in[11];
    float* out = (float*)d_out;

    cudaFuncSetAttribute(mma_gemm_kernel<0>, cudaFuncAttributeMaxDynamicSharedMemorySize, SM_TOTAL);
    cudaFuncSetAttribute(mma_gemm_kernel<1>, cudaFuncAttributeMaxDynamicSharedMemorySize, SM_TOTAL);
    cudaFuncSetAttribute(gated_mma_kernel,   cudaFuncAttributeMaxDynamicSharedMemorySize, SM_TOTAL);

    // routing metadata
    init_kernel<<<(ROWS_PAD_MAX + 255) / 256, 256>>>();
    gate_kernel<<<T_TOK / 8, 256>>>(x, gate_w);
    scan_kernel<<<1, 32>>>();
    assign_kernel<<<(T_TOK + 255) / 256, 256>>>();

    __half* xh;  cudaGetSymbolAddress((void**)&xh,  g_xh);
    __half* f1h; cudaGetSymbolAddress((void**)&f1h, g_f1h);
    __half* f2h; cudaGetSymbolAddress((void**)&f2h, g_f2h);
    __half* w1h; cudaGetSymbolAddress((void**)&w1h, g_w1h);
    __half* w3h; cudaGetSymbolAddress((void**)&w3h, g_w3h);
    __half* w2h; cudaGetSymbolAddress((void**)&w2h, g_w2h);
    __half* Hh;  cudaGetSymbolAddress((void**)&Hh,  g_H);
    __half* Gp;  cudaGetSymbolAddress((void**)&Gp,  g_Gp);
    float* Yf;  cudaGetSymbolAddress((void**)&Yf,  g_Y);

    // single fused conversion pass (x + all weights)
    conv6_kernel<<<(O6 + 255) / 256, 256>>>(x, fc1_w, fc2_w, w1_w, w3_w, w2_w);

    // routed experts
    mma_gemm_kernel<0><<<dim3(ROW_TILES, FF / GBN), 256, SM_TOTAL>>>(
        xh, f1h, fc1_b, nullptr, Hh, DIM, FF, 1, 1);
    mma_gemm_kernel<1><<<dim3(ROW_TILES, DIM / GBN), 256, SM_TOTAL>>>(
        Hh, f2h, fc2_b, Yf, nullptr, FF, DIM, 1, 0);

    // shared gated MLP: fused w1+w3+eltwise, then w2
    gated_mma_kernel<<<dim3(T_TOK / GBM, FF / 64), 256, SM_TOTAL>>>(
        xh, w1h, w3h, w1_b, w3_b, Gp);
    mma_gemm_kernel<1><<<dim3(T_TOK / GBM, DIM / GBN), 256, SM_TOTAL>>>(
        Gp, w2h, w2_b, out, nullptr, FF, DIM, 0, 0);

    // combine
    combine_kernel<<<(int)(((size_t)T_TOK * DIM + 255) / 256), 256>>>(out);
}

// round 14
// speedup vs baseline: 1.5338x; 1.0241x over previous
#include <cuda_runtime.h>
#include <cuda_fp16.h>
#include <math.h>
#include <stdint.h>

// ---------------- problem constants ----------------
#define T_TOK   16384
#define DIM     768
#define FF      2048
#define NE      8
#define SLOTS   (2*T_TOK)
#define BM      128
#define ROWS_PAD_MAX (SLOTS + NE*BM)   // 33792
#define ROW_TILES    (ROWS_PAD_MAX/BM) // 264

// GEMM tiling (R8-proven: 3 stages, two syncs per K-chunk)
#define GBM 128
#define GBN 128
#define GBK 32                  // K elements per stage chunk (64 bytes/row fp16)
#define ROWB 80                 // padded row stride bytes (64 data + 16 pad)
#define MATB (128*ROWB)         // 10240 bytes per 128-row matrix per stage
#define HMATB (64*ROWB)         // 5120 bytes per 64-row matrix per stage
#define STAGEB (2*MATB)         // 20480: A + B   (gated: A + B1 + B3 = same size)
#define STAGES 3
#define SM_BIAS (STAGES*STAGEB) // 61440
#define SM_TOTAL (SM_BIAS + 512)

// conversion segment sizes in float4 units
#define C_X   (T_TOK*DIM/4)
#define C_F1  (NE*FF*DIM/4)
#define C_F2  (NE*DIM*FF/4)
#define C_W   (FF*DIM/4)
#define O1 (C_X)
#define O2 (O1 + C_F1)
#define O3 (O2 + C_F2)
#define O4 (O3 + C_W)
#define O5 (O4 + C_W)
#define O6 (O5 + C_W)

// ---------------- device scratch ----------------
__device__ __half g_xh [(size_t)T_TOK * DIM];
__device__ __half g_f1h[(size_t)NE * FF * DIM];
__device__ __half g_f2h[(size_t)NE * DIM * FF];
__device__ __half g_w1h[(size_t)FF * DIM];
__device__ __half g_w3h[(size_t)FF * DIM];
__device__ __half g_w2h[(size_t)DIM * FF];
__device__ __half g_H  [(size_t)ROWS_PAD_MAX * FF];
__device__ __half g_Gp [(size_t)T_TOK * FF];
__device__ float g_Y [(size_t)ROWS_PAD_MAX * DIM];
__device__ int   g_rowtoken[ROWS_PAD_MAX];
__device__ int   g_rowmap[SLOTS];
__device__ float g_slotw[SLOTS];
__device__ int   g_slote[SLOTS];
__device__ int   g_counts[NE];
__device__ int   g_cursor[NE];
__device__ int   g_base[NE+1];

__device__ __forceinline__ float gelu_exact(float v) {
    return 0.5f * v * (1.0f + erff(v * 0.7071067811865475f));
}

// ---------------- PTX helpers (sm_80+ portable) ----------------
__device__ __forceinline__ uint32_t smem_u32(const void* p) {
    uint32_t a;
    asm("{ .reg .u64 t; cvta.to.shared.u64 t, %1; cvt.u32.u64 %0, t; }" : "=r"(a) : "l"(p));
    return a;
}
#define CP16(sa, gp) asm volatile("cp.async.cg.shared.global [%0], [%1], 16;" :: "r"(sa), "l"(gp))
#define CP_COMMIT()  asm volatile("cp.async.commit_group;" ::: "memory")
#define CP_WAIT2()   asm volatile("cp.async.wait_group 2;" ::: "memory")

#define LDSM4(r, a) \
    asm volatile("ldmatrix.sync.aligned.m8n8.x4.shared.b16 {%0,%1,%2,%3}, [%4];" \
        : "=r"((r)[0]), "=r"((r)[1]), "=r"((r)[2]), "=r"((r)[3]) : "r"(a))

__device__ __forceinline__ void mma_f16(float* c, const uint32_t* a, const uint32_t* b) {
    asm volatile(
        "mma.sync.aligned.m16n8k16.row.col.f32.f16.f16.f32 "
        "{%0,%1,%2,%3}, {%4,%5,%6,%7}, {%8,%9}, {%0,%1,%2,%3};"
        : "+f"(c[0]), "+f"(c[1]), "+f"(c[2]), "+f"(c[3])
        : "r"(a[0]), "r"(a[1]), "r"(a[2]), "r"(a[3]), "r"(b[0]), "r"(b[1]));
}

// ---------------- small kernels ----------------
__global__ void init_kernel() {
    int i = blockIdx.x * blockDim.x + threadIdx.x;
    if (i < ROWS_PAD_MAX) g_rowtoken[i] = -1;
    if (i < NE) { g_counts[i] = 0; g_cursor[i] = 0; }
}

// gate (no fused conversion)
__global__ __launch_bounds__(256) void gate_kernel(const float* __restrict__ x,
                                                   const float* __restrict__ gw) {
    __shared__ float sgw[NE * DIM];
    for (int i = threadIdx.x; i < NE * DIM; i += 256) sgw[i] = gw[i];
    __syncthreads();
    int warp = threadIdx.x >> 5, lane = threadIdx.x & 31;
    int t = blockIdx.x * 8 + warp;
    if (t >= T_TOK) return;
    const float* xr = x + (size_t)t * DIM;
    float xv[24];
#pragma unroll
    for (int j = 0; j < 24; j++) xv[j] = xr[lane + 32 * j];
    float logit[NE];
#pragma unroll
    for (int e = 0; e < NE; e++) {
        float p = 0.f;
#pragma unroll
        for (int j = 0; j < 24; j++) p += xv[j] * sgw[e * DIM + lane + 32 * j];
#pragma unroll
        for (int off = 16; off > 0; off >>= 1) p += __shfl_down_sync(0xffffffffu, p, off);
        logit[e] = p;
    }
    if (lane == 0) {
        float m = logit[0];
#pragma unroll
        for (int e = 1; e < NE; e++) m = fmaxf(m, logit[e]);
        int a = 0;
#pragma unroll
        for (int e = 1; e < NE; e++) if (logit[e] > logit[a]) a = e;
        int b = (a == 0) ? 1 : 0;
#pragma unroll
        for (int e = 0; e < NE; e++) { if (e == a || e == b) continue; if (logit[e] > logit[b]) b = e; }
        float pa = expf(logit[a] - m), pb = expf(logit[b] - m);
        float inv = 1.f / (pa + pb);
        g_slote[2 * t] = a;  g_slote[2 * t + 1] = b;
        g_slotw[2 * t] = pa * inv;  g_slotw[2 * t + 1] = pb * inv;
        atomicAdd(&g_counts[a], 1);
        atomicAdd(&g_counts[b], 1);
    }
}

__global__ void scan_kernel() {
    if (threadIdx.x == 0 && blockIdx.x == 0) {
        int b = 0; g_base[0] = 0;
        for (int e = 0; e < NE; e++) {
            b += ((g_counts[e] + BM - 1) / BM) * BM;
            g_base[e + 1] = b;
        }
    }
}

__global__ void assign_kernel() {
    int t = blockIdx.x * blockDim.x + threadIdx.x;
    if (t >= T_TOK) return;
#pragma unroll
    for (int k = 0; k < 2; k++) {
        int e = g_slote[2 * t + k];
        int pos = atomicAdd(&g_cursor[e], 1);
        int row = g_base[e] + pos;
        g_rowmap[2 * t + k] = row;
        g_rowtoken[row] = t;
    }
}

// single fused fp32 -> fp16 conversion over all 6 tensors
__global__ void conv6_kernel(const float* __restrict__ x,
                             const float* __restrict__ f1, const float* __restrict__ f2,
                             const float* __restrict__ w1, const float* __restrict__ w3,
                             const float* __restrict__ w2) {
    int i = blockIdx.x * blockDim.x + threadIdx.x;
    if (i >= O6) return;
    const float* s; __half* d; int off;
    if (i < O1)      { s = x;  d = g_xh;  off = i; }
    else if (i < O2) { s = f1; d = g_f1h; off = i - O1; }
    else if (i < O3) { s = f2; d = g_f2h; off = i - O2; }
    else if (i < O4) { s = w1; d = g_w1h; off = i - O3; }
    else if (i < O5) { s = w3; d = g_w3h; off = i - O4; }
    else             { s = w2; d = g_w2h; off = i - O5; }
    float4 v = ((const float4*)s)[off];
    __half h[4];
    h[0] = __float2half_rn(v.x); h[1] = __float2half_rn(v.y);
    h[2] = __float2half_rn(v.z); h[3] = __float2half_rn(v.w);
    ((uint2*)d)[off] = *(uint2*)h;
}

// ---------------- mma.sync fp16 GEMM (R8-proven 3-stage schedule) ----------------
// C[M,N] = A[M,K] x B[N,K]^T + bias
// MODE 0: gelu(acc+bias) -> fp16 Ch
// MODE 1: acc+bias -> fp32 Cf
// MODE 3: out = (acc+bias) + w0*Y[row0] + w1*Y[row1]   [w2 + combine fusion]
template<int MODE>
__global__ __launch_bounds__(256, 2) void mma_gemm_kernel(
    const __half* __restrict__ A, const __half* __restrict__ B,
    const float* __restrict__ bias,
    float* __restrict__ Cf, __half* __restrict__ Ch,
    int K, int N, int expert_mode, int gather)
{
    extern __shared__ char smem[];
    uint32_t sb = smem_u32(smem);
    int tid = threadIdx.x;

    int rstart = blockIdx.x * GBM;
    int n0 = blockIdx.y * GBN;

    if (expert_mode) {
        if (rstart >= g_base[NE]) return;
        int e = 0;
#pragma unroll
        for (int i = 0; i < NE; i++) if (rstart >= g_base[i + 1]) e = i + 1;
        B += (size_t)e * N * K;
        bias += (size_t)e * N;
    }

    // loads: thread t loads row t/2, 32B half (t&1)
    int lrow = tid >> 1;
    int lcb  = (tid & 1) * 32;
    int arow_g;
    if (gather) {
        int tok = g_rowtoken[rstart + lrow];
        arow_g = (tok < 0) ? 0 : tok;
    } else {
        arow_g = rstart + lrow;
    }
    const char* pA = (const char*)(A + (size_t)arow_g * K) + lcb;
    const char* pB = (const char*)(B + (size_t)(n0 + lrow) * K) + lcb;
    uint32_t sA = sb + (uint32_t)(lrow * ROWB + lcb);

    if (tid < 128) ((float*)(smem + SM_BIAS))[tid] = bias[n0 + tid];

    int nk = K / GBK;

#define ISSUE(kc, s) do { \
    uint32_t o = (uint32_t)(s) * STAGEB; \
    size_t g = (size_t)(kc) * 64; \
    CP16(sA + o,          pA + g); CP16(sA + o + 16,        pA + g + 16); \
    CP16(sA + o + MATB,   pB + g); CP16(sA + o + MATB + 16, pB + g + 16); \
    CP_COMMIT(); } while (0)

    ISSUE(0, 0);
    ISSUE(1, 1);
    ISSUE(2, 2);

    int wid = tid >> 5, lane = tid & 31;
    int wm = (wid & 3) * 32;
    int wn = (wid >> 2) * 64;
    int lq = lane >> 2;
    int lr = lane & 3;

    uint32_t aoff[2], boff[4];
#pragma unroll
    for (int m = 0; m < 2; m++)
        aoff[m] = (uint32_t)((wm + m * 16 + (lane & 15)) * ROWB + ((lane >> 4) << 4));
#pragma unroll
    for (int p = 0; p < 4; p++)
        boff[p] = (uint32_t)((wn + p * 16 + (lane & 7) + ((lane & 16) ? 8 : 0)) * ROWB
                             + ((lane & 8) ? 16 : 0));

    float acc[2][8][4];
#pragma unroll
    for (int m = 0; m < 2; m++)
#pragma unroll
        for (int n = 0; n < 8; n++)
#pragma unroll
            for (int j = 0; j < 4; j++) acc[m][n][j] = 0.f;

    // R8-proven mainloop: wait -> sync -> compute -> sync -> issue
    for (int kc = 0; kc < nk; kc++) {
        CP_WAIT2();
        __syncthreads();
        uint32_t st = sb + (uint32_t)(kc % STAGES) * STAGEB;
#pragma unroll
        for (int ks = 0; ks < 2; ks++) {
            uint32_t ko = (uint32_t)(ks * 32);
            uint32_t a[2][4];
            LDSM4(a[0], st + aoff[0] + ko);
            LDSM4(a[1], st + aoff[1] + ko);
#pragma unroll
            for (int p = 0; p < 4; p++) {
                uint32_t bh[4];
                LDSM4(bh, st + MATB + boff[p] + ko);
#pragma unroll
                for (int m = 0; m < 2; m++) {
                    mma_f16(acc[m][2 * p],     a[m], bh);
                    mma_f16(acc[m][2 * p + 1], a[m], bh + 2);
                }
            }
        }
        __syncthreads();
        if (kc + STAGES < nk) { ISSUE(kc + STAGES, kc % STAGES); }
        else { CP_COMMIT(); }
    }
#undef ISSUE

    const float* sbias = (const float*)(smem + SM_BIAS);
#pragma unroll
    for (int m = 0; m < 2; m++) {
        int r0 = rstart + wm + m * 16 + lq;
        int ra0 = 0, rb0 = 0, ra1 = 0, rb1 = 0;
        float wa0 = 0.f, wb0 = 0.f, wa1 = 0.f, wb1 = 0.f;
        if (MODE == 3) {
            ra0 = g_rowmap[2 * r0];           wa0 = g_slotw[2 * r0];
            rb0 = g_rowmap[2 * r0 + 1];       wb0 = g_slotw[2 * r0 + 1];
            ra1 = g_rowmap[2 * (r0 + 8)];     wa1 = g_slotw[2 * (r0 + 8)];
            rb1 = g_rowmap[2 * (r0 + 8) + 1]; wb1 = g_slotw[2 * (r0 + 8) + 1];
        }
#pragma unroll
        for (int n = 0; n < 8; n++) {
            int col = wn + n * 8 + lr * 2;
            float b0 = sbias[col], b1 = sbias[col + 1];
            int gc = n0 + col;
            float v00 = acc[m][n][0] + b0, v01 = acc[m][n][1] + b1;
            float v10 = acc[m][n][2] + b0, v11 = acc[m][n][3] + b1;
            if (MODE == 1) {
                *(float2*)&Cf[(size_t)r0 * N + gc]       = make_float2(v00, v01);
                *(float2*)&Cf[(size_t)(r0 + 8) * N + gc] = make_float2(v10, v11);
            } else if (MODE == 0) {
                __half2 h0, h1;
                h0.x = __float2half_rn(gelu_exact(v00));
                h0.y = __float2half_rn(gelu_exact(v01));
                h1.x = __float2half_rn(gelu_exact(v10));
                h1.y = __float2half_rn(gelu_exact(v11));
                *(__half2*)&Ch[(size_t)r0 * N + gc]       = h0;
                *(__half2*)&Ch[(size_t)(r0 + 8) * N + gc] = h1;
            } else {
                float2 ya0 = *(const float2*)&g_Y[(size_t)ra0 * DIM + gc];
                float2 yb0 = *(const float2*)&g_Y[(size_t)rb0 * DIM + gc];
                float2 ya1 = *(const float2*)&g_Y[(size_t)ra1 * DIM + gc];
                float2 yb1 = *(const float2*)&g_Y[(size_t)rb1 * DIM + gc];
                float2 o0, o1;
                o0.x = v00 + wa0 * ya0.x + wb0 * yb0.x;
                o0.y = v01 + wa0 * ya0.y + wb0 * yb0.y;
                o1.x = v10 + wa1 * ya1.x + wb1 * yb1.x;
                o1.y = v11 + wa1 * ya1.y + wb1 * yb1.y;
                *(float2*)&Cf[(size_t)r0 * N + gc]       = o0;
                *(float2*)&Cf[(size_t)(r0 + 8) * N + gc] = o1;
            }
        }
    }
}

// ---------------- fused w1/w3 gated MLP front (R8-proven 3-stage schedule) ----------------
__global__ __launch_bounds__(256, 2) void gated_mma_kernel(
    const __half* __restrict__ A,
    const __half* __restrict__ B1, const __half* __restrict__ B3,
    const float* __restrict__ bias1, const float* __restrict__ bias3,
    __half* __restrict__ Gp)
{
    extern __shared__ char smem[];
    uint32_t sb = smem_u32(smem);
    int tid = threadIdx.x;
    int rstart = blockIdx.x * GBM;
    int n0 = blockIdx.y * 64;

    int lrow = tid >> 1;
    int lcb  = (tid & 1) * 32;
    const char* pA = (const char*)(A + (size_t)(rstart + lrow) * DIM) + lcb;
    uint32_t sA = sb + (uint32_t)(lrow * ROWB + lcb);
    int brow = tid >> 2;
    int bq   = (tid & 3) * 16;
    const char* pB1 = (const char*)(B1 + (size_t)(n0 + brow) * DIM) + bq;
    const char* pB3 = (const char*)(B3 + (size_t)(n0 + brow) * DIM) + bq;
    uint32_t sB = sb + (uint32_t)(brow * ROWB + bq);

    if (tid < 64) {
        ((float*)(smem + SM_BIAS))[tid]      = bias1[n0 + tid];
        ((float*)(smem + SM_BIAS))[64 + tid] = bias3[n0 + tid];
    }

    const int nk = DIM / GBK;

#define ISSUE_G(kc, s) do { \
    uint32_t o = (uint32_t)(s) * STAGEB; \
    size_t g = (size_t)(kc) * 64; \
    CP16(sA + o,                pA  + g); CP16(sA + o + 16, pA + g + 16); \
    CP16(sB + o + MATB,         pB1 + g); \
    CP16(sB + o + MATB + HMATB, pB3 + g); \
    CP_COMMIT(); } while (0)

    ISSUE_G(0, 0);
    ISSUE_G(1, 1);
    ISSUE_G(2, 2);

    int wid = tid >> 5, lane = tid & 31;
    int wm = (wid & 3) * 32;
    int wn = (wid >> 2) * 32;
    int lq = lane >> 2;
    int lr = lane & 3;

    uint32_t aoff[2], boff[2];
#pragma unroll
    for (int m = 0; m < 2; m++)
        aoff[m] = (uint32_t)((wm + m * 16 + (lane & 15)) * ROWB + ((lane >> 4) << 4));
#pragma unroll
    for (int p = 0; p < 2; p++)
        boff[p] = (uint32_t)((wn + p * 16 + (lane & 7) + ((lane & 16) ? 8 : 0)) * ROWB
                             + ((lane & 8) ? 16 : 0));

    float acc1[2][4][4], acc3[2][4][4];
#pragma unroll
    for (int m = 0; m < 2; m++)
#pragma unroll
        for (int n = 0; n < 4; n++)
#pragma unroll
            for (int j = 0; j < 4; j++) { acc1[m][n][j] = 0.f; acc3[m][n][j] = 0.f; }

    for (int kc = 0; kc < nk; kc++) {
        CP_WAIT2();
        __syncthreads();
        uint32_t st = sb + (uint32_t)(kc % STAGES) * STAGEB;
#pragma unroll
        for (int ks = 0; ks < 2; ks++) {
            uint32_t ko = (uint32_t)(ks * 32);
            uint32_t a[2][4];
            LDSM4(a[0], st + aoff[0] + ko);
            LDSM4(a[1], st + aoff[1] + ko);
#pragma unroll
            for (int p = 0; p < 2; p++) {
                uint32_t b1[4], b3[4];
                LDSM4(b1, st + MATB + boff[p] + ko);
                LDSM4(b3, st + MATB + HMATB + boff[p] + ko);
#pragma unroll
                for (int m = 0; m < 2; m++) {
                    mma_f16(acc1[m][2 * p],     a[m], b1);
                    mma_f16(acc1[m][2 * p + 1], a[m], b1 + 2);
                    mma_f16(acc3[m][2 * p],     a[m], b3);
                    mma_f16(acc3[m][2 * p + 1], a[m], b3 + 2);
                }
            }
        }
        __syncthreads();
        if (kc + STAGES < nk) { ISSUE_G(kc + STAGES, kc % STAGES); }
        else { CP_COMMIT(); }
    }
#undef ISSUE_G

    const float* b1s = (const float*)(smem + SM_BIAS);
    const float* b3s = b1s + 64;
#pragma unroll
    for (int m = 0; m < 2; m++) {
        int r0 = rstart + wm + m * 16 + lq;
#pragma unroll
        for (int n = 0; n < 4; n++) {
            int col = wn + n * 8 + lr * 2;
            float c10 = b1s[col], c11 = b1s[col + 1];
            float c30 = b3s[col], c31 = b3s[col + 1];
            int gc = n0 + col;
            __half2 h0, h1;
            h0.x = __float2half_rn(gelu_exact(acc1[m][n][0] + c10) * (acc3[m][n][0] + c30));
            h0.y = __float2half_rn(gelu_exact(acc1[m][n][1] + c11) * (acc3[m][n][1] + c31));
            h1.x = __float2half_rn(gelu_exact(acc1[m][n][2] + c10) * (acc3[m][n][2] + c30));
            h1.y = __float2half_rn(gelu_exact(acc1[m][n][3] + c11) * (acc3[m][n][3] + c31));
            *(__half2*)&Gp[(size_t)r0 * FF + gc]       = h0;
            *(__half2*)&Gp[(size_t)(r0 + 8) * FF + gc] = h1;
        }
    }
}

// ---------------- launch ----------------
extern "C" void kernel_launch(void* const* d_in, const int* in_sizes, int n_in,
                              void* d_out, int out_size) {
    const float* x      = (const float*)d_in[0];
    const float* gate_w = (const float*)d_in[1];
    const float* fc1_w  = (const float*)d_in[2];
    const float* fc1_b  = (const float*)d_in[3];
    const float* fc2_w  = (const float*)d_in[4];
    const float* fc2_b  = (const float*)d_in[5];
    const float* w1_w   = (const float*)d_in[6];
    const float* w1_b   = (const float*)d_in[7];
    const float* w3_w   = (const float*)d_in[8];
    const float* w3_b   = (const float*)d_in[9];
    const float* w2_w   = (const float*)d_in[10];
    const float* w2_b   = (const float*)d_in[11];
    float* out = (float*)d_out;

    cudaFuncSetAttribute(mma_gemm_kernel<0>, cudaFuncAttributeMaxDynamicSharedMemorySize, SM_TOTAL);
    cudaFuncSetAttribute(mma_gemm_kernel<1>, cudaFuncAttributeMaxDynamicSharedMemorySize, SM_TOTAL);
    cudaFuncSetAttribute(mma_gemm_kernel<3>, cudaFuncAttributeMaxDynamicSharedMemorySize, SM_TOTAL);
    cudaFuncSetAttribute(gated_mma_kernel,   cudaFuncAttributeMaxDynamicSharedMemorySize, SM_TOTAL);

    // routing metadata
    init_kernel<<<(ROWS_PAD_MAX + 255) / 256, 256>>>();
    gate_kernel<<<T_TOK / 8, 256>>>(x, gate_w);
    scan_kernel<<<1, 32>>>();
    assign_kernel<<<(T_TOK + 255) / 256, 256>>>();

    __half* xh;  cudaGetSymbolAddress((void**)&xh,  g_xh);
    __half* f1h; cudaGetSymbolAddress((void**)&f1h, g_f1h);
    __half* f2h; cudaGetSymbolAddress((void**)&f2h, g_f2h);
    __half* w1h; cudaGetSymbolAddress((void**)&w1h, g_w1h);
    __half* w3h; cudaGetSymbolAddress((void**)&w3h, g_w3h);
    __half* w2h; cudaGetSymbolAddress((void**)&w2h, g_w2h);
    __half* Hh;  cudaGetSymbolAddress((void**)&Hh,  g_H);
    __half* Gp;  cudaGetSymbolAddress((void**)&Gp,  g_Gp);
    float* Yf;  cudaGetSymbolAddress((void**)&Yf,  g_Y);

    // single fused conversion pass (x + all weights)
    conv6_kernel<<<(O6 + 255) / 256, 256>>>(x, fc1_w, fc2_w, w1_w, w3_w, w2_w);

    // routed experts: fc1 -> H (gelu fp16), fc2 -> g_Y (fp32)
    mma_gemm_kernel<0><<<dim3(ROW_TILES, FF / GBN), 256, SM_TOTAL>>>(
        xh, f1h, fc1_b, nullptr, Hh, DIM, FF, 1, 1);
    mma_gemm_kernel<1><<<dim3(ROW_TILES, DIM / GBN), 256, SM_TOTAL>>>(
        Hh, f2h, fc2_b, Yf, nullptr, FF, DIM, 1, 0);

    // shared gated MLP: fused w1+w3+eltwise, then w2 with fused combine epilogue
    gated_mma_kernel<<<dim3(T_TOK / GBM, FF / 64), 256, SM_TOTAL>>>(
        xh, w1h, w3h, w1_b, w3_b, Gp);
    mma_gemm_kernel<3><<<dim3(T_TOK / GBM, DIM / GBN), 256, SM_TOTAL>>>(
        Gp, w2h, w2_b, out, nullptr, FF, DIM, 0, 0);
}